// round 11
// baseline (speedup 1.0000x reference)
#include <cuda_runtime.h>
#include <cuda_fp16.h>

#define NN   50000
#define NE   1250000
#define HID  64
#define NL   3
#define NG   64
#define EPSV 1e-5f
#define CAP  80          // max in-degree bucket capacity (Poisson(25): P(>80) ~ 1e-20)
#define GR   128         // gemm rows per block tile

// -------- device scratch (no runtime allocation allowed) --------
__device__ unsigned int d_hhA[NN * 32];     // half2 node features (128B/row)
__device__ unsigned int d_hhB[NN * 32];
__device__ unsigned int d_hhM[NN * 32];     // m = h @ W (half2)
__device__ int2  d_bkt[NN * CAP];           // per-dst edge buckets: (src, w-bits)
__device__ int   d_cnt[NN];                 // per-dst degree counters
__device__ float d_psum[NG * HID];
__device__ int   d_pmax[NG * HID];          // float bits; post-ReLU values >= 0
__device__ int   d_pcnt[NG];

// -------- prep: zero counters/pools + convert emb fp32 -> half2 --------
__global__ void prep_kernel(const float* __restrict__ emb) {
    int i = blockIdx.x * blockDim.x + threadIdx.x;
    int stride = gridDim.x * blockDim.x;
    for (int k = i; k < NN * 32; k += stride) {
        float2 v = ((const float2*)emb)[k];
        __half2 h = __floats2half2_rn(v.x, v.y);
        d_hhA[k] = *(unsigned int*)&h;
    }
    for (int k = i; k < NN; k += stride) d_cnt[k] = 0;
    for (int k = i; k < NG * HID; k += stride) { d_psum[k] = 0.f; d_pmax[k] = 0; }
    if (i < NG) d_pcnt[i] = 0;
}

// -------- bucket scatter: count + place edges in one pass (4-way MLP) ------
__global__ void scatter_kernel(const int* __restrict__ src, const int* __restrict__ dst,
                               const float* __restrict__ w, int ne, int T) {
    int t = blockIdx.x * blockDim.x + threadIdx.x;
    if (t >= T) return;
    int e0 = t, e1 = t + T, e2 = t + 2 * T, e3 = t + 3 * T;
    int d0 = (e0 < ne) ? dst[e0] : -1;
    int d1 = (e1 < ne) ? dst[e1] : -1;
    int d2 = (e2 < ne) ? dst[e2] : -1;
    int d3 = (e3 < ne) ? dst[e3] : -1;
    int s0 = (e0 < ne) ? src[e0] : 0;
    int s1 = (e1 < ne) ? src[e1] : 0;
    int s2 = (e2 < ne) ? src[e2] : 0;
    int s3 = (e3 < ne) ? src[e3] : 0;
    float w0 = (e0 < ne) ? w[e0] : 0.f;
    float w1 = (e1 < ne) ? w[e1] : 0.f;
    float w2 = (e2 < ne) ? w[e2] : 0.f;
    float w3 = (e3 < ne) ? w[e3] : 0.f;
    if (d0 >= 0) { int p = atomicAdd(&d_cnt[d0], 1); if (p < CAP) d_bkt[d0 * CAP + p] = make_int2(s0, __float_as_int(w0)); }
    if (d1 >= 0) { int p = atomicAdd(&d_cnt[d1], 1); if (p < CAP) d_bkt[d1 * CAP + p] = make_int2(s1, __float_as_int(w1)); }
    if (d2 >= 0) { int p = atomicAdd(&d_cnt[d2], 1); if (p < CAP) d_bkt[d2 * CAP + p] = make_int2(s2, __float_as_int(w2)); }
    if (d3 >= 0) { int p = atomicAdd(&d_cnt[d3], 1); if (p < CAP) d_bkt[d3 * CAP + p] = make_int2(s3, __float_as_int(w3)); }
}

__device__ __forceinline__ float2 h2f(unsigned int bits) {
    __half2 h = *(__half2*)&bits;
    return __half22float2(h);
}

// -------- dense GEMM: m(fp16) = h(fp16) @ W(fp32) -------------------------
__global__ void __launch_bounds__(256)
gemm_kernel(const unsigned int* __restrict__ hin, const float* __restrict__ W,
            unsigned int* __restrict__ mout, int n) {
    __shared__ float Ws[HID * HID];                 // 16 KB
    __shared__ __half hs[GR][HID + 2];              // pad -> conflict-free
    int t = threadIdx.x;
    for (int i = t; i < HID * HID; i += 256) Ws[i] = W[i];
    int row0 = blockIdx.x * GR;
    for (int i = t; i < GR * 32; i += 256) {
        int r = i >> 5, c = i & 31;
        unsigned int bits = 0;
        int gr = row0 + r;
        if (gr < n) bits = hin[(size_t)gr * 32 + c];
        *(unsigned int*)&hs[r][c * 2] = bits;
    }
    __syncthreads();

    int tx = t & 7;        // cols tx*8 .. tx*8+7
    int ty = t >> 3;       // rows ty, ty+32, ty+64, ty+96
    float acc[4][8];
#pragma unroll
    for (int r = 0; r < 4; r++)
#pragma unroll
        for (int j = 0; j < 8; j++) acc[r][j] = 0.f;

#pragma unroll 8
    for (int k = 0; k < HID; k++) {
        float4 wa = *(const float4*)&Ws[k * HID + tx * 8];
        float4 wb = *(const float4*)&Ws[k * HID + tx * 8 + 4];
        float hv[4];
        hv[0] = __half2float(hs[ty][k]);
        hv[1] = __half2float(hs[ty + 32][k]);
        hv[2] = __half2float(hs[ty + 64][k]);
        hv[3] = __half2float(hs[ty + 96][k]);
#pragma unroll
        for (int r = 0; r < 4; r++) {
            acc[r][0] += hv[r] * wa.x;
            acc[r][1] += hv[r] * wa.y;
            acc[r][2] += hv[r] * wa.z;
            acc[r][3] += hv[r] * wa.w;
            acc[r][4] += hv[r] * wb.x;
            acc[r][5] += hv[r] * wb.y;
            acc[r][6] += hv[r] * wb.z;
            acc[r][7] += hv[r] * wb.w;
        }
    }

#pragma unroll
    for (int r = 0; r < 4; r++) {
        int gr = row0 + ty + r * 32;
        if (gr < n) {
#pragma unroll
            for (int j = 0; j < 4; j++) {
                __half2 hv = __floats2half2_rn(acc[r][2 * j], acc[r][2 * j + 1]);
                mout[(size_t)gr * 32 + tx * 4 + j] = *(unsigned int*)&hv;
            }
        }
    }
}

// -------- aggregate(m) -> +b -> LN -> ReLU [-> pool] ----------------------
// ONE node per warp; the two 16-lane halves process two consecutive edges of
// the SAME node (rows gathered as uint2 over 16 lanes). One LDG.64 serves two
// edges -> LDG instruction count per edge halves vs the 32-lane gather.
__global__ void __launch_bounds__(256)
agg_kernel(const unsigned int* __restrict__ m,
           const float* __restrict__ cB,
           const float* __restrict__ lg,
           const float* __restrict__ lb,
           unsigned int* __restrict__ hout,
           const int* __restrict__ batch,
           int do_pool, int n) {
    __shared__ float sB[HID], sG[HID], sLb[HID];
    int t = threadIdx.x;
    if (t < HID) { sB[t] = cB[t]; sG[t] = lg[t]; sLb[t] = lb[t]; }
    __syncthreads();

    int warp = t >> 5, lane = t & 31;
    int h = lane >> 4, sub = lane & 15;
    int nwarp = blockDim.x >> 5;
    const uint2* m2 = (const uint2*)m;

    for (int node = blockIdx.x * nwarp + warp; node < n; node += gridDim.x * nwarp) {
        int cnt = min(d_cnt[node], CAP);
        const int2* eb = d_bkt + (size_t)node * CAP;

        float4 acc = make_float4(0.f, 0.f, 0.f, 0.f);
        // 8 edges per iteration: 4 (desc,gather) LDG.64 pairs, both halves active
        for (int base = 0; base < cnt; base += 8) {
            int2 p[4];
#pragma unroll
            for (int u = 0; u < 4; u++) {
                int idx = base + 2 * u + h;
                p[u] = (idx < cnt) ? eb[idx] : make_int2(0, 0);  // w=0 pad: row-0 gather, L1-hot
            }
            uint2 g[4];
#pragma unroll
            for (int u = 0; u < 4; u++)
                g[u] = __ldg(m2 + (size_t)p[u].x * 16 + sub);
#pragma unroll
            for (int u = 0; u < 4; u++) {
                float w = __int_as_float(p[u].y);
                float2 v0 = h2f(g[u].x);
                float2 v1 = h2f(g[u].y);
                acc.x += v0.x * w; acc.y += v0.y * w;
                acc.z += v1.x * w; acc.w += v1.y * w;
            }
        }

        // merge the two 16-lane halves (they hold even/odd edge partials)
        acc.x += __shfl_xor_sync(0xffffffffu, acc.x, 16);
        acc.y += __shfl_xor_sync(0xffffffffu, acc.y, 16);
        acc.z += __shfl_xor_sync(0xffffffffu, acc.z, 16);
        acc.w += __shfl_xor_sync(0xffffffffu, acc.w, 16);

        // bias
        float4 b4 = *(const float4*)&sB[sub * 4];
        acc.x += b4.x; acc.y += b4.y; acc.z += b4.z; acc.w += b4.w;

        // LayerNorm over 64 (16-lane reduction; both halves redundant) + ReLU
        float sum = (acc.x + acc.y) + (acc.z + acc.w);
#pragma unroll
        for (int o = 8; o > 0; o >>= 1) sum += __shfl_xor_sync(0xffffffffu, sum, o);
        float mu = sum * (1.f / 64.f);
        float dx0 = acc.x - mu, dx1 = acc.y - mu, dx2 = acc.z - mu, dx3 = acc.w - mu;
        float v2 = (dx0 * dx0 + dx1 * dx1) + (dx2 * dx2 + dx3 * dx3);
#pragma unroll
        for (int o = 8; o > 0; o >>= 1) v2 += __shfl_xor_sync(0xffffffffu, v2, o);
        float inv = rsqrtf(v2 * (1.f / 64.f) + EPSV);
        float4 g4 = *(const float4*)&sG[sub * 4];
        float4 l4 = *(const float4*)&sLb[sub * 4];
        float r0 = fmaxf(dx0 * inv * g4.x + l4.x, 0.f);
        float r1 = fmaxf(dx1 * inv * g4.y + l4.y, 0.f);
        float r2 = fmaxf(dx2 * inv * g4.z + l4.z, 0.f);
        float r3 = fmaxf(dx3 * inv * g4.w + l4.w, 0.f);

        if (h == 0) {   // low half owns the output
            if (do_pool) {
                int b = batch[node];
                int c0 = b * HID + sub * 4;
                atomicAdd(&d_psum[c0 + 0], r0);
                atomicAdd(&d_psum[c0 + 1], r1);
                atomicAdd(&d_psum[c0 + 2], r2);
                atomicAdd(&d_psum[c0 + 3], r3);
                atomicMax(&d_pmax[c0 + 0], __float_as_int(r0));
                atomicMax(&d_pmax[c0 + 1], __float_as_int(r1));
                atomicMax(&d_pmax[c0 + 2], __float_as_int(r2));
                atomicMax(&d_pmax[c0 + 3], __float_as_int(r3));
                if (sub == 0) atomicAdd(&d_pcnt[b], 1);
            } else {
                __half2 o0 = __floats2half2_rn(r0, r1);
                __half2 o1 = __floats2half2_rn(r2, r3);
                uint2 ov = make_uint2(*(unsigned int*)&o0, *(unsigned int*)&o1);
                ((uint2*)hout)[(size_t)node * 16 + sub] = ov;
            }
        }
    }
}

// -------- final MLP --------
__global__ void mlp_kernel(const float* __restrict__ W1, const float* __restrict__ b1,
                           const float* __restrict__ W2, const float* __restrict__ b2,
                           float* __restrict__ out) {
    __shared__ float g[2 * HID];
    __shared__ float hr[HID];
    int gi = blockIdx.x, j = threadIdx.x;
    int cnt = d_pcnt[gi];
    float c = fmaxf((float)cnt, 1.f);
    g[j] = d_psum[gi * HID + j] / c;
    g[HID + j] = (cnt > 0) ? __int_as_float(d_pmax[gi * HID + j]) : 0.f;
    __syncthreads();
    float acc = b1[j];
#pragma unroll
    for (int k = 0; k < 2 * HID; k++) acc += g[k] * W1[k * HID + j];
    acc = fmaxf(acc, 0.f);
    hr[j] = acc * W2[j];
    __syncthreads();
    if (j < 32) {
        float s = hr[j] + hr[j + 32];
#pragma unroll
        for (int o = 16; o > 0; o >>= 1) s += __shfl_xor_sync(0xffffffffu, s, o);
        if (j == 0) out[gi] = s + b2[0];
    }
}

extern "C" void kernel_launch(void* const* d_in, const int* in_sizes, int n_in,
                              void* d_out, int out_size) {
    const int*   edge_index = (const int*)d_in[1];
    const float* edge_w     = (const float*)d_in[2];
    const int*   batch      = (const int*)d_in[3];
    const float* emb        = (const float*)d_in[4];
    const float* convW      = (const float*)d_in[5];
    const float* convB      = (const float*)d_in[6];
    const float* lnG        = (const float*)d_in[7];
    const float* lnB        = (const float*)d_in[8];
    const float* W1         = (const float*)d_in[9];
    const float* b1         = (const float*)d_in[10];
    const float* W2         = (const float*)d_in[11];
    const float* b2         = (const float*)d_in[12];
    float* out = (float*)d_out;

    int ne = in_sizes[2];
    int n  = in_sizes[3];
    const int* src = edge_index;
    const int* dst = edge_index + ne;

    unsigned int *hA, *hB, *hM;
    cudaGetSymbolAddress((void**)&hA, d_hhA);
    cudaGetSymbolAddress((void**)&hB, d_hhB);
    cudaGetSymbolAddress((void**)&hM, d_hhM);

    prep_kernel<<<1184, 256>>>(emb);
    int T = (ne + 3) / 4;
    scatter_kernel<<<(T + 255) / 256, 256>>>(src, dst, edge_w, ne, T);

    const int THREADS = 256;
    const int WARPS_PER_BLK = THREADS / 32;
    int agg_blocks = (n + 4 * WARPS_PER_BLK - 1) / (4 * WARPS_PER_BLK);   // R8 grid: 1563
    int gemm_blocks = (n + GR - 1) / GR;

    // L0: hA -> m -> hB ; L1: hB -> m -> hA ; L2: hA -> m -> pool
    gemm_kernel<<<gemm_blocks, THREADS>>>(hA, convW + 0 * HID * HID, hM, n);
    agg_kernel<<<agg_blocks, THREADS>>>(hM, convB + 0 * HID, lnG + 0 * HID,
                                        lnB + 0 * HID, hB, batch, 0, n);
    gemm_kernel<<<gemm_blocks, THREADS>>>(hB, convW + 1 * HID * HID, hM, n);
    agg_kernel<<<agg_blocks, THREADS>>>(hM, convB + 1 * HID, lnG + 1 * HID,
                                        lnB + 1 * HID, hA, batch, 0, n);
    gemm_kernel<<<gemm_blocks, THREADS>>>(hA, convW + 2 * HID * HID, hM, n);
    agg_kernel<<<agg_blocks, THREADS>>>(hM, convB + 2 * HID, lnG + 2 * HID,
                                        lnB + 2 * HID, (unsigned int*)nullptr, batch, 1, n);

    mlp_kernel<<<NG, HID>>>(W1, b1, W2, b2, out);
}

// round 12
// speedup vs baseline: 1.2236x; 1.2236x over previous
#include <cuda_runtime.h>
#include <cuda_fp16.h>

#define NN   50000
#define NE   1250000
#define HID  64
#define NL   3
#define NG   64
#define EPSV 1e-5f
#define CAP  80          // max in-degree bucket capacity (Poisson(25): P(>80) ~ 1e-20)
#define GR   128         // gemm rows per block tile

// -------- device scratch (no runtime allocation allowed) --------
__device__ unsigned int d_hhA[NN * 32];     // half2 node features (128B/row)
__device__ unsigned int d_hhB[NN * 32];
__device__ unsigned int d_hhM[NN * 32];     // m = h @ W (half2)
__device__ int2  d_bkt[NN * CAP];           // per-dst edge buckets: (src, w-bits)
__device__ int   d_cnt[NN];                 // per-dst degree counters
__device__ float d_psum[NG * HID];
__device__ int   d_pmax[NG * HID];          // float bits; post-ReLU values >= 0
__device__ int   d_pcnt[NG];

// -------- prep: zero counters/pools + convert emb fp32 -> half2 --------
__global__ void prep_kernel(const float* __restrict__ emb) {
    int i = blockIdx.x * blockDim.x + threadIdx.x;
    int stride = gridDim.x * blockDim.x;
    for (int k = i; k < NN * 32; k += stride) {
        float2 v = ((const float2*)emb)[k];
        __half2 h = __floats2half2_rn(v.x, v.y);
        d_hhA[k] = *(unsigned int*)&h;
    }
    for (int k = i; k < NN; k += stride) d_cnt[k] = 0;
    for (int k = i; k < NG * HID; k += stride) { d_psum[k] = 0.f; d_pmax[k] = 0; }
    if (i < NG) d_pcnt[i] = 0;
}

// -------- bucket scatter: count + place edges in one pass (4-way MLP) ------
__global__ void scatter_kernel(const int* __restrict__ src, const int* __restrict__ dst,
                               const float* __restrict__ w, int ne, int T) {
    int t = blockIdx.x * blockDim.x + threadIdx.x;
    if (t >= T) return;
    int e0 = t, e1 = t + T, e2 = t + 2 * T, e3 = t + 3 * T;
    int d0 = (e0 < ne) ? dst[e0] : -1;
    int d1 = (e1 < ne) ? dst[e1] : -1;
    int d2 = (e2 < ne) ? dst[e2] : -1;
    int d3 = (e3 < ne) ? dst[e3] : -1;
    int s0 = (e0 < ne) ? src[e0] : 0;
    int s1 = (e1 < ne) ? src[e1] : 0;
    int s2 = (e2 < ne) ? src[e2] : 0;
    int s3 = (e3 < ne) ? src[e3] : 0;
    float w0 = (e0 < ne) ? w[e0] : 0.f;
    float w1 = (e1 < ne) ? w[e1] : 0.f;
    float w2 = (e2 < ne) ? w[e2] : 0.f;
    float w3 = (e3 < ne) ? w[e3] : 0.f;
    if (d0 >= 0) { int p = atomicAdd(&d_cnt[d0], 1); if (p < CAP) d_bkt[d0 * CAP + p] = make_int2(s0, __float_as_int(w0)); }
    if (d1 >= 0) { int p = atomicAdd(&d_cnt[d1], 1); if (p < CAP) d_bkt[d1 * CAP + p] = make_int2(s1, __float_as_int(w1)); }
    if (d2 >= 0) { int p = atomicAdd(&d_cnt[d2], 1); if (p < CAP) d_bkt[d2 * CAP + p] = make_int2(s2, __float_as_int(w2)); }
    if (d3 >= 0) { int p = atomicAdd(&d_cnt[d3], 1); if (p < CAP) d_bkt[d3 * CAP + p] = make_int2(s3, __float_as_int(w3)); }
}

__device__ __forceinline__ float2 h2f(unsigned int bits) {
    __half2 h = *(__half2*)&bits;
    return __half22float2(h);
}

// -------- dense GEMM: m(fp16) = h(fp16) @ W(fp32) -------------------------
__global__ void __launch_bounds__(256)
gemm_kernel(const unsigned int* __restrict__ hin, const float* __restrict__ W,
            unsigned int* __restrict__ mout, int n) {
    __shared__ float Ws[HID * HID];                 // 16 KB
    __shared__ __half hs[GR][HID + 2];              // pad -> conflict-free
    int t = threadIdx.x;
    for (int i = t; i < HID * HID; i += 256) Ws[i] = W[i];
    int row0 = blockIdx.x * GR;
    for (int i = t; i < GR * 32; i += 256) {
        int r = i >> 5, c = i & 31;
        unsigned int bits = 0;
        int gr = row0 + r;
        if (gr < n) bits = hin[(size_t)gr * 32 + c];
        *(unsigned int*)&hs[r][c * 2] = bits;
    }
    __syncthreads();

    int tx = t & 7;        // cols tx*8 .. tx*8+7
    int ty = t >> 3;       // rows ty, ty+32, ty+64, ty+96
    float acc[4][8];
#pragma unroll
    for (int r = 0; r < 4; r++)
#pragma unroll
        for (int j = 0; j < 8; j++) acc[r][j] = 0.f;

#pragma unroll 8
    for (int k = 0; k < HID; k++) {
        float4 wa = *(const float4*)&Ws[k * HID + tx * 8];
        float4 wb = *(const float4*)&Ws[k * HID + tx * 8 + 4];
        float hv[4];
        hv[0] = __half2float(hs[ty][k]);
        hv[1] = __half2float(hs[ty + 32][k]);
        hv[2] = __half2float(hs[ty + 64][k]);
        hv[3] = __half2float(hs[ty + 96][k]);
#pragma unroll
        for (int r = 0; r < 4; r++) {
            acc[r][0] += hv[r] * wa.x;
            acc[r][1] += hv[r] * wa.y;
            acc[r][2] += hv[r] * wa.z;
            acc[r][3] += hv[r] * wa.w;
            acc[r][4] += hv[r] * wb.x;
            acc[r][5] += hv[r] * wb.y;
            acc[r][6] += hv[r] * wb.z;
            acc[r][7] += hv[r] * wb.w;
        }
    }

#pragma unroll
    for (int r = 0; r < 4; r++) {
        int gr = row0 + ty + r * 32;
        if (gr < n) {
#pragma unroll
            for (int j = 0; j < 4; j++) {
                __half2 hv = __floats2half2_rn(acc[r][2 * j], acc[r][2 * j + 1]);
                mout[(size_t)gr * 32 + tx * 4 + j] = *(unsigned int*)&hv;
            }
        }
    }
}

// -------- aggregate(m) -> +b -> LN -> ReLU [-> pool] ----------------------
// One node per warp (R8 layout). Descriptors loaded as int4 (2 edges/LDG.128)
// -> 1.5 LDG instructions per edge instead of 2.
__global__ void __launch_bounds__(256)
agg_kernel(const unsigned int* __restrict__ m,
           const float* __restrict__ cB,
           const float* __restrict__ lg,
           const float* __restrict__ lb,
           unsigned int* __restrict__ hout,
           const int* __restrict__ batch,
           int do_pool, int n) {
    __shared__ float sB[HID], sG[HID], sLb[HID];
    int t = threadIdx.x;
    if (t < HID) { sB[t] = cB[t]; sG[t] = lg[t]; sLb[t] = lb[t]; }
    __syncthreads();

    int warp = t >> 5, lane = t & 31;
    int nwarp = blockDim.x >> 5;

    for (int node = blockIdx.x * nwarp + warp; node < n; node += gridDim.x * nwarp) {
        int cnt = min(d_cnt[node], CAP);
        const int2* eb = d_bkt + (size_t)node * CAP;
        float ax = 0.f, ay = 0.f;
        int e = 0;
        for (; e + 8 <= cnt; e += 8) {
            // 4x LDG.128 descriptor loads (2 edges each), 16B-aligned
            int4 q0 = ((const int4*)(eb + e))[0];
            int4 q1 = ((const int4*)(eb + e))[1];
            int4 q2 = ((const int4*)(eb + e))[2];
            int4 q3 = ((const int4*)(eb + e))[3];
            unsigned int g0 = __ldg(m + (size_t)q0.x * 32 + lane);
            unsigned int g1 = __ldg(m + (size_t)q0.z * 32 + lane);
            unsigned int g2 = __ldg(m + (size_t)q1.x * 32 + lane);
            unsigned int g3 = __ldg(m + (size_t)q1.z * 32 + lane);
            unsigned int g4 = __ldg(m + (size_t)q2.x * 32 + lane);
            unsigned int g5 = __ldg(m + (size_t)q2.z * 32 + lane);
            unsigned int g6 = __ldg(m + (size_t)q3.x * 32 + lane);
            unsigned int g7 = __ldg(m + (size_t)q3.z * 32 + lane);
            float2 v;
            v = h2f(g0); ax += v.x * __int_as_float(q0.y); ay += v.y * __int_as_float(q0.y);
            v = h2f(g1); ax += v.x * __int_as_float(q0.w); ay += v.y * __int_as_float(q0.w);
            v = h2f(g2); ax += v.x * __int_as_float(q1.y); ay += v.y * __int_as_float(q1.y);
            v = h2f(g3); ax += v.x * __int_as_float(q1.w); ay += v.y * __int_as_float(q1.w);
            v = h2f(g4); ax += v.x * __int_as_float(q2.y); ay += v.y * __int_as_float(q2.y);
            v = h2f(g5); ax += v.x * __int_as_float(q2.w); ay += v.y * __int_as_float(q2.w);
            v = h2f(g6); ax += v.x * __int_as_float(q3.y); ay += v.y * __int_as_float(q3.y);
            v = h2f(g7); ax += v.x * __int_as_float(q3.w); ay += v.y * __int_as_float(q3.w);
        }
        for (; e < cnt; e++) {
            int2 p = eb[e];
            unsigned int g = __ldg(m + (size_t)p.x * 32 + lane);
            float2 v = h2f(g);
            float w = __int_as_float(p.y);
            ax += v.x * w; ay += v.y * w;
        }

        float accx = ax + sB[2 * lane];
        float accy = ay + sB[2 * lane + 1];

        // LayerNorm over 64 + ReLU
        float sum = accx + accy;
#pragma unroll
        for (int o = 16; o > 0; o >>= 1) sum += __shfl_xor_sync(0xffffffffu, sum, o);
        float mu = sum * (1.f / 64.f);
        float dx = accx - mu, dy = accy - mu;
        float v2 = dx * dx + dy * dy;
#pragma unroll
        for (int o = 16; o > 0; o >>= 1) v2 += __shfl_xor_sync(0xffffffffu, v2, o);
        float inv = rsqrtf(v2 * (1.f / 64.f) + EPSV);
        float rx = fmaxf(dx * inv * sG[2 * lane] + sLb[2 * lane], 0.f);
        float ry = fmaxf(dy * inv * sG[2 * lane + 1] + sLb[2 * lane + 1], 0.f);

        if (do_pool) {
            int b = batch[node];
            atomicAdd(&d_psum[b * HID + 2 * lane], rx);
            atomicAdd(&d_psum[b * HID + 2 * lane + 1], ry);
            atomicMax(&d_pmax[b * HID + 2 * lane], __float_as_int(rx));
            atomicMax(&d_pmax[b * HID + 2 * lane + 1], __float_as_int(ry));
            if (lane == 0) atomicAdd(&d_pcnt[b], 1);
        } else {
            __half2 hv = __floats2half2_rn(rx, ry);
            hout[(size_t)node * 32 + lane] = *(unsigned int*)&hv;
        }
    }
}

// -------- final MLP --------
__global__ void mlp_kernel(const float* __restrict__ W1, const float* __restrict__ b1,
                           const float* __restrict__ W2, const float* __restrict__ b2,
                           float* __restrict__ out) {
    __shared__ float g[2 * HID];
    __shared__ float hr[HID];
    int gi = blockIdx.x, j = threadIdx.x;
    int cnt = d_pcnt[gi];
    float c = fmaxf((float)cnt, 1.f);
    g[j] = d_psum[gi * HID + j] / c;
    g[HID + j] = (cnt > 0) ? __int_as_float(d_pmax[gi * HID + j]) : 0.f;
    __syncthreads();
    float acc = b1[j];
#pragma unroll
    for (int k = 0; k < 2 * HID; k++) acc += g[k] * W1[k * HID + j];
    acc = fmaxf(acc, 0.f);
    hr[j] = acc * W2[j];
    __syncthreads();
    if (j < 32) {
        float s = hr[j] + hr[j + 32];
#pragma unroll
        for (int o = 16; o > 0; o >>= 1) s += __shfl_xor_sync(0xffffffffu, s, o);
        if (j == 0) out[gi] = s + b2[0];
    }
}

extern "C" void kernel_launch(void* const* d_in, const int* in_sizes, int n_in,
                              void* d_out, int out_size) {
    const int*   edge_index = (const int*)d_in[1];
    const float* edge_w     = (const float*)d_in[2];
    const int*   batch      = (const int*)d_in[3];
    const float* emb        = (const float*)d_in[4];
    const float* convW      = (const float*)d_in[5];
    const float* convB      = (const float*)d_in[6];
    const float* lnG        = (const float*)d_in[7];
    const float* lnB        = (const float*)d_in[8];
    const float* W1         = (const float*)d_in[9];
    const float* b1         = (const float*)d_in[10];
    const float* W2         = (const float*)d_in[11];
    const float* b2         = (const float*)d_in[12];
    float* out = (float*)d_out;

    int ne = in_sizes[2];
    int n  = in_sizes[3];
    const int* src = edge_index;
    const int* dst = edge_index + ne;

    unsigned int *hA, *hB, *hM;
    cudaGetSymbolAddress((void**)&hA, d_hhA);
    cudaGetSymbolAddress((void**)&hB, d_hhB);
    cudaGetSymbolAddress((void**)&hM, d_hhM);

    prep_kernel<<<1184, 256>>>(emb);
    int T = (ne + 3) / 4;
    scatter_kernel<<<(T + 255) / 256, 256>>>(src, dst, edge_w, ne, T);

    const int THREADS = 256;
    // wave-balanced grid: exactly 8 blocks per SM (148 SMs), grid-stride
    int agg_blocks = 1184;
    int gemm_blocks = (n + GR - 1) / GR;

    // L0: hA -> m -> hB ; L1: hB -> m -> hA ; L2: hA -> m -> pool
    gemm_kernel<<<gemm_blocks, THREADS>>>(hA, convW + 0 * HID * HID, hM, n);
    agg_kernel<<<agg_blocks, THREADS>>>(hM, convB + 0 * HID, lnG + 0 * HID,
                                        lnB + 0 * HID, hB, batch, 0, n);
    gemm_kernel<<<gemm_blocks, THREADS>>>(hB, convW + 1 * HID * HID, hM, n);
    agg_kernel<<<agg_blocks, THREADS>>>(hM, convB + 1 * HID, lnG + 1 * HID,
                                        lnB + 1 * HID, hA, batch, 0, n);
    gemm_kernel<<<gemm_blocks, THREADS>>>(hA, convW + 2 * HID * HID, hM, n);
    agg_kernel<<<agg_blocks, THREADS>>>(hM, convB + 2 * HID, lnG + 2 * HID,
                                        lnB + 2 * HID, (unsigned int*)nullptr, batch, 1, n);

    mlp_kernel<<<NG, HID>>>(W1, b1, W2, b2, out);
}

// round 13
// speedup vs baseline: 1.2238x; 1.0002x over previous
#include <cuda_runtime.h>
#include <cuda_fp16.h>

#define NN   50000
#define NE   1250000
#define HID  64
#define NL   3
#define NG   64
#define EPSV 1e-5f
#define CAP  80          // max in-degree bucket capacity (Poisson(25): P(>80) ~ 1e-20)
#define GR   128         // gemm rows per block tile

// -------- device scratch (no runtime allocation allowed) --------
__device__ unsigned int d_hhA[NN * 32];     // half2 node features (128B/row)
__device__ unsigned int d_hhB[NN * 32];
__device__ unsigned int d_hhM[NN * 32];     // m = h @ W (half2)
__device__ int2  d_bkt[NN * CAP];           // per-dst edge buckets: (src, w-bits)
__device__ int   d_cnt[NN];                 // per-dst degree counters
__device__ float d_psum[NG * HID];
__device__ int   d_pmax[NG * HID];          // float bits; post-ReLU values >= 0
__device__ int   d_pcnt[NG];

// -------- prep: zero counters/pools + convert emb fp32 -> half2 --------
__global__ void prep_kernel(const float* __restrict__ emb) {
    int i = blockIdx.x * blockDim.x + threadIdx.x;
    int stride = gridDim.x * blockDim.x;
    for (int k = i; k < NN * 32; k += stride) {
        float2 v = ((const float2*)emb)[k];
        __half2 h = __floats2half2_rn(v.x, v.y);
        d_hhA[k] = *(unsigned int*)&h;
    }
    for (int k = i; k < NN; k += stride) d_cnt[k] = 0;
    for (int k = i; k < NG * HID; k += stride) { d_psum[k] = 0.f; d_pmax[k] = 0; }
    if (i < NG) d_pcnt[i] = 0;
}

// -------- bucket scatter: count + place edges in one pass (4-way MLP) ------
__global__ void scatter_kernel(const int* __restrict__ src, const int* __restrict__ dst,
                               const float* __restrict__ w, int ne, int T) {
    int t = blockIdx.x * blockDim.x + threadIdx.x;
    if (t >= T) return;
    int e0 = t, e1 = t + T, e2 = t + 2 * T, e3 = t + 3 * T;
    int d0 = (e0 < ne) ? dst[e0] : -1;
    int d1 = (e1 < ne) ? dst[e1] : -1;
    int d2 = (e2 < ne) ? dst[e2] : -1;
    int d3 = (e3 < ne) ? dst[e3] : -1;
    int s0 = (e0 < ne) ? src[e0] : 0;
    int s1 = (e1 < ne) ? src[e1] : 0;
    int s2 = (e2 < ne) ? src[e2] : 0;
    int s3 = (e3 < ne) ? src[e3] : 0;
    float w0 = (e0 < ne) ? w[e0] : 0.f;
    float w1 = (e1 < ne) ? w[e1] : 0.f;
    float w2 = (e2 < ne) ? w[e2] : 0.f;
    float w3 = (e3 < ne) ? w[e3] : 0.f;
    if (d0 >= 0) { int p = atomicAdd(&d_cnt[d0], 1); if (p < CAP) d_bkt[d0 * CAP + p] = make_int2(s0, __float_as_int(w0)); }
    if (d1 >= 0) { int p = atomicAdd(&d_cnt[d1], 1); if (p < CAP) d_bkt[d1 * CAP + p] = make_int2(s1, __float_as_int(w1)); }
    if (d2 >= 0) { int p = atomicAdd(&d_cnt[d2], 1); if (p < CAP) d_bkt[d2 * CAP + p] = make_int2(s2, __float_as_int(w2)); }
    if (d3 >= 0) { int p = atomicAdd(&d_cnt[d3], 1); if (p < CAP) d_bkt[d3 * CAP + p] = make_int2(s3, __float_as_int(w3)); }
}

__device__ __forceinline__ float2 h2f(unsigned int bits) {
    __half2 h = *(__half2*)&bits;
    return __half22float2(h);
}

// -------- dense GEMM: m(fp16) = h(fp16) @ W(fp32) -------------------------
__global__ void __launch_bounds__(256)
gemm_kernel(const unsigned int* __restrict__ hin, const float* __restrict__ W,
            unsigned int* __restrict__ mout, int n) {
    __shared__ float Ws[HID * HID];                 // 16 KB
    __shared__ __half hs[GR][HID + 2];              // pad -> conflict-free
    int t = threadIdx.x;
    for (int i = t; i < HID * HID; i += 256) Ws[i] = W[i];
    int row0 = blockIdx.x * GR;
    for (int i = t; i < GR * 32; i += 256) {
        int r = i >> 5, c = i & 31;
        unsigned int bits = 0;
        int gr = row0 + r;
        if (gr < n) bits = hin[(size_t)gr * 32 + c];
        *(unsigned int*)&hs[r][c * 2] = bits;
    }
    __syncthreads();

    int tx = t & 7;        // cols tx*8 .. tx*8+7
    int ty = t >> 3;       // rows ty, ty+32, ty+64, ty+96
    float acc[4][8];
#pragma unroll
    for (int r = 0; r < 4; r++)
#pragma unroll
        for (int j = 0; j < 8; j++) acc[r][j] = 0.f;

#pragma unroll 8
    for (int k = 0; k < HID; k++) {
        float4 wa = *(const float4*)&Ws[k * HID + tx * 8];
        float4 wb = *(const float4*)&Ws[k * HID + tx * 8 + 4];
        float hv[4];
        hv[0] = __half2float(hs[ty][k]);
        hv[1] = __half2float(hs[ty + 32][k]);
        hv[2] = __half2float(hs[ty + 64][k]);
        hv[3] = __half2float(hs[ty + 96][k]);
#pragma unroll
        for (int r = 0; r < 4; r++) {
            acc[r][0] += hv[r] * wa.x;
            acc[r][1] += hv[r] * wa.y;
            acc[r][2] += hv[r] * wa.z;
            acc[r][3] += hv[r] * wa.w;
            acc[r][4] += hv[r] * wb.x;
            acc[r][5] += hv[r] * wb.y;
            acc[r][6] += hv[r] * wb.z;
            acc[r][7] += hv[r] * wb.w;
        }
    }

#pragma unroll
    for (int r = 0; r < 4; r++) {
        int gr = row0 + ty + r * 32;
        if (gr < n) {
#pragma unroll
            for (int j = 0; j < 4; j++) {
                __half2 hv = __floats2half2_rn(acc[r][2 * j], acc[r][2 * j + 1]);
                mout[(size_t)gr * 32 + tx * 4 + j] = *(unsigned int*)&hv;
            }
        }
    }
}

// -------- aggregate(m) -> +b -> LN -> ReLU [-> pool] ----------------------
// One node per warp. Deep-window gather: 16-edge batches (8x int4 desc loads,
// 16 independent gathers in flight), then 8-batch and scalar tails.
__global__ void
agg_kernel(const unsigned int* __restrict__ m,
           const float* __restrict__ cB,
           const float* __restrict__ lg,
           const float* __restrict__ lb,
           unsigned int* __restrict__ hout,
           const int* __restrict__ batch,
           int do_pool, int n) {
    __shared__ float sB[HID], sG[HID], sLb[HID];
    int t = threadIdx.x;
    if (t < HID) { sB[t] = cB[t]; sG[t] = lg[t]; sLb[t] = lb[t]; }
    __syncthreads();

    int warp = t >> 5, lane = t & 31;
    int nwarp = blockDim.x >> 5;

    for (int node = blockIdx.x * nwarp + warp; node < n; node += gridDim.x * nwarp) {
        int cnt = min(d_cnt[node], CAP);
        const int2* eb = d_bkt + (size_t)node * CAP;
        float ax = 0.f, ay = 0.f;
        int e = 0;

        // 16-edge deep batches
        for (; e + 16 <= cnt; e += 16) {
            int4 q[8];
#pragma unroll
            for (int u = 0; u < 8; u++) q[u] = ((const int4*)(eb + e))[u];
            unsigned int g[16];
#pragma unroll
            for (int u = 0; u < 8; u++) {
                g[2 * u]     = __ldg(m + (size_t)q[u].x * 32 + lane);
                g[2 * u + 1] = __ldg(m + (size_t)q[u].z * 32 + lane);
            }
#pragma unroll
            for (int u = 0; u < 8; u++) {
                float2 v;
                v = h2f(g[2 * u]);
                ax += v.x * __int_as_float(q[u].y); ay += v.y * __int_as_float(q[u].y);
                v = h2f(g[2 * u + 1]);
                ax += v.x * __int_as_float(q[u].w); ay += v.y * __int_as_float(q[u].w);
            }
        }
        // 8-edge batch
        for (; e + 8 <= cnt; e += 8) {
            int4 q0 = ((const int4*)(eb + e))[0];
            int4 q1 = ((const int4*)(eb + e))[1];
            int4 q2 = ((const int4*)(eb + e))[2];
            int4 q3 = ((const int4*)(eb + e))[3];
            unsigned int g0 = __ldg(m + (size_t)q0.x * 32 + lane);
            unsigned int g1 = __ldg(m + (size_t)q0.z * 32 + lane);
            unsigned int g2 = __ldg(m + (size_t)q1.x * 32 + lane);
            unsigned int g3 = __ldg(m + (size_t)q1.z * 32 + lane);
            unsigned int g4 = __ldg(m + (size_t)q2.x * 32 + lane);
            unsigned int g5 = __ldg(m + (size_t)q2.z * 32 + lane);
            unsigned int g6 = __ldg(m + (size_t)q3.x * 32 + lane);
            unsigned int g7 = __ldg(m + (size_t)q3.z * 32 + lane);
            float2 v;
            v = h2f(g0); ax += v.x * __int_as_float(q0.y); ay += v.y * __int_as_float(q0.y);
            v = h2f(g1); ax += v.x * __int_as_float(q0.w); ay += v.y * __int_as_float(q0.w);
            v = h2f(g2); ax += v.x * __int_as_float(q1.y); ay += v.y * __int_as_float(q1.y);
            v = h2f(g3); ax += v.x * __int_as_float(q1.w); ay += v.y * __int_as_float(q1.w);
            v = h2f(g4); ax += v.x * __int_as_float(q2.y); ay += v.y * __int_as_float(q2.y);
            v = h2f(g5); ax += v.x * __int_as_float(q2.w); ay += v.y * __int_as_float(q2.w);
            v = h2f(g6); ax += v.x * __int_as_float(q3.y); ay += v.y * __int_as_float(q3.y);
            v = h2f(g7); ax += v.x * __int_as_float(q3.w); ay += v.y * __int_as_float(q3.w);
        }
        // scalar tail
        for (; e < cnt; e++) {
            int2 p = eb[e];
            unsigned int g = __ldg(m + (size_t)p.x * 32 + lane);
            float2 v = h2f(g);
            float w = __int_as_float(p.y);
            ax += v.x * w; ay += v.y * w;
        }

        float accx = ax + sB[2 * lane];
        float accy = ay + sB[2 * lane + 1];

        // LayerNorm over 64 + ReLU
        float sum = accx + accy;
#pragma unroll
        for (int o = 16; o > 0; o >>= 1) sum += __shfl_xor_sync(0xffffffffu, sum, o);
        float mu = sum * (1.f / 64.f);
        float dx = accx - mu, dy = accy - mu;
        float v2 = dx * dx + dy * dy;
#pragma unroll
        for (int o = 16; o > 0; o >>= 1) v2 += __shfl_xor_sync(0xffffffffu, v2, o);
        float inv = rsqrtf(v2 * (1.f / 64.f) + EPSV);
        float rx = fmaxf(dx * inv * sG[2 * lane] + sLb[2 * lane], 0.f);
        float ry = fmaxf(dy * inv * sG[2 * lane + 1] + sLb[2 * lane + 1], 0.f);

        if (do_pool) {
            int b = batch[node];
            atomicAdd(&d_psum[b * HID + 2 * lane], rx);
            atomicAdd(&d_psum[b * HID + 2 * lane + 1], ry);
            atomicMax(&d_pmax[b * HID + 2 * lane], __float_as_int(rx));
            atomicMax(&d_pmax[b * HID + 2 * lane + 1], __float_as_int(ry));
            if (lane == 0) atomicAdd(&d_pcnt[b], 1);
        } else {
            __half2 hv = __floats2half2_rn(rx, ry);
            hout[(size_t)node * 32 + lane] = *(unsigned int*)&hv;
        }
    }
}

// -------- final MLP --------
__global__ void mlp_kernel(const float* __restrict__ W1, const float* __restrict__ b1,
                           const float* __restrict__ W2, const float* __restrict__ b2,
                           float* __restrict__ out) {
    __shared__ float g[2 * HID];
    __shared__ float hr[HID];
    int gi = blockIdx.x, j = threadIdx.x;
    int cnt = d_pcnt[gi];
    float c = fmaxf((float)cnt, 1.f);
    g[j] = d_psum[gi * HID + j] / c;
    g[HID + j] = (cnt > 0) ? __int_as_float(d_pmax[gi * HID + j]) : 0.f;
    __syncthreads();
    float acc = b1[j];
#pragma unroll
    for (int k = 0; k < 2 * HID; k++) acc += g[k] * W1[k * HID + j];
    acc = fmaxf(acc, 0.f);
    hr[j] = acc * W2[j];
    __syncthreads();
    if (j < 32) {
        float s = hr[j] + hr[j + 32];
#pragma unroll
        for (int o = 16; o > 0; o >>= 1) s += __shfl_xor_sync(0xffffffffu, s, o);
        if (j == 0) out[gi] = s + b2[0];
    }
}

extern "C" void kernel_launch(void* const* d_in, const int* in_sizes, int n_in,
                              void* d_out, int out_size) {
    const int*   edge_index = (const int*)d_in[1];
    const float* edge_w     = (const float*)d_in[2];
    const int*   batch      = (const int*)d_in[3];
    const float* emb        = (const float*)d_in[4];
    const float* convW      = (const float*)d_in[5];
    const float* convB      = (const float*)d_in[6];
    const float* lnG        = (const float*)d_in[7];
    const float* lnB        = (const float*)d_in[8];
    const float* W1         = (const float*)d_in[9];
    const float* b1         = (const float*)d_in[10];
    const float* W2         = (const float*)d_in[11];
    const float* b2         = (const float*)d_in[12];
    float* out = (float*)d_out;

    int ne = in_sizes[2];
    int n  = in_sizes[3];
    const int* src = edge_index;
    const int* dst = edge_index + ne;

    unsigned int *hA, *hB, *hM;
    cudaGetSymbolAddress((void**)&hA, d_hhA);
    cudaGetSymbolAddress((void**)&hB, d_hhB);
    cudaGetSymbolAddress((void**)&hM, d_hhM);

    prep_kernel<<<1184, 256>>>(emb);
    int T = (ne + 3) / 4;
    scatter_kernel<<<(T + 255) / 256, 256>>>(src, dst, edge_w, ne, T);

    const int THREADS = 256;
    int agg_blocks = 1184;                  // 8 blocks/SM wave-balanced grid-stride
    int gemm_blocks = (n + GR - 1) / GR;

    // L0: hA -> m -> hB ; L1: hB -> m -> hA ; L2: hA -> m -> pool
    gemm_kernel<<<gemm_blocks, THREADS>>>(hA, convW + 0 * HID * HID, hM, n);
    agg_kernel<<<agg_blocks, THREADS>>>(hM, convB + 0 * HID, lnG + 0 * HID,
                                        lnB + 0 * HID, hB, batch, 0, n);
    gemm_kernel<<<gemm_blocks, THREADS>>>(hB, convW + 1 * HID * HID, hM, n);
    agg_kernel<<<agg_blocks, THREADS>>>(hM, convB + 1 * HID, lnG + 1 * HID,
                                        lnB + 1 * HID, hA, batch, 0, n);
    gemm_kernel<<<gemm_blocks, THREADS>>>(hA, convW + 2 * HID * HID, hM, n);
    agg_kernel<<<agg_blocks, THREADS>>>(hM, convB + 2 * HID, lnG + 2 * HID,
                                        lnB + 2 * HID, (unsigned int*)nullptr, batch, 1, n);

    mlp_kernel<<<NG, HID>>>(W1, b1, W2, b2, out);
}

// round 14
// speedup vs baseline: 1.2598x; 1.0294x over previous
#include <cuda_runtime.h>
#include <cuda_fp16.h>

#define NN   50000
#define NE   1250000
#define HID  64
#define NL   3
#define NG   64
#define EPSV 1e-5f
#define CAP  80          // max in-degree bucket capacity (Poisson(25): P(>80) ~ 1e-20)
#define TR   64          // rows (nodes) per layer-kernel block tile

// -------- device scratch (no runtime allocation allowed) --------
__device__ unsigned int d_hhA[NN * 32];     // half2 node features (128B/row)
__device__ unsigned int d_hhB[NN * 32];
__device__ int2  d_bkt[NN * CAP];           // per-dst edge buckets: (src, w-bits)
__device__ int   d_cnt[NN];                 // per-dst degree counters
__device__ float d_psum[NG * HID];
__device__ int   d_pmax[NG * HID];          // float bits; post-ReLU values >= 0
__device__ int   d_pcnt[NG];

// -------- prep: zero counters/pools + convert emb fp32 -> half2 --------
__global__ void prep_kernel(const float* __restrict__ emb) {
    int i = blockIdx.x * blockDim.x + threadIdx.x;
    int stride = gridDim.x * blockDim.x;
    for (int k = i; k < NN * 32; k += stride) {
        float2 v = ((const float2*)emb)[k];
        __half2 h = __floats2half2_rn(v.x, v.y);
        d_hhA[k] = *(unsigned int*)&h;
    }
    for (int k = i; k < NN; k += stride) d_cnt[k] = 0;
    for (int k = i; k < NG * HID; k += stride) { d_psum[k] = 0.f; d_pmax[k] = 0; }
    if (i < NG) d_pcnt[i] = 0;
}

// -------- bucket scatter: count + place edges in one pass (4-way MLP) ------
__global__ void scatter_kernel(const int* __restrict__ src, const int* __restrict__ dst,
                               const float* __restrict__ w, int ne, int T) {
    int t = blockIdx.x * blockDim.x + threadIdx.x;
    if (t >= T) return;
    int e0 = t, e1 = t + T, e2 = t + 2 * T, e3 = t + 3 * T;
    int d0 = (e0 < ne) ? dst[e0] : -1;
    int d1 = (e1 < ne) ? dst[e1] : -1;
    int d2 = (e2 < ne) ? dst[e2] : -1;
    int d3 = (e3 < ne) ? dst[e3] : -1;
    int s0 = (e0 < ne) ? src[e0] : 0;
    int s1 = (e1 < ne) ? src[e1] : 0;
    int s2 = (e2 < ne) ? src[e2] : 0;
    int s3 = (e3 < ne) ? src[e3] : 0;
    float w0 = (e0 < ne) ? w[e0] : 0.f;
    float w1 = (e1 < ne) ? w[e1] : 0.f;
    float w2 = (e2 < ne) ? w[e2] : 0.f;
    float w3 = (e3 < ne) ? w[e3] : 0.f;
    if (d0 >= 0) { int p = atomicAdd(&d_cnt[d0], 1); if (p < CAP) d_bkt[d0 * CAP + p] = make_int2(s0, __float_as_int(w0)); }
    if (d1 >= 0) { int p = atomicAdd(&d_cnt[d1], 1); if (p < CAP) d_bkt[d1 * CAP + p] = make_int2(s1, __float_as_int(w1)); }
    if (d2 >= 0) { int p = atomicAdd(&d_cnt[d2], 1); if (p < CAP) d_bkt[d2 * CAP + p] = make_int2(s2, __float_as_int(w2)); }
    if (d3 >= 0) { int p = atomicAdd(&d_cnt[d3], 1); if (p < CAP) d_bkt[d3 * CAP + p] = make_int2(s3, __float_as_int(w3)); }
}

__device__ __forceinline__ float2 h2f(unsigned int bits) {
    __half2 h = *(__half2*)&bits;
    return __half22float2(h);
}

// -------- fused layer: aggregate raw h -> smem tile -> @W -> +b -> LN ------
//          -> ReLU -> store fp16 (or pool).
// Phase 1: 8 warps aggregate 8 nodes each (R12-style int4/gather loop) into
//          a [64][66] fp32 smem tile.
// Phase 2: register-tiled 64x64 GEMM from smem (thread = 4 rows x 4 cols),
//          bias + LN (16-lane shfl) + ReLU, write half2 rows (or pool atomics).
__global__ void __launch_bounds__(256)
layer_kernel(const unsigned int* __restrict__ hin,
             const float* __restrict__ W,
             const float* __restrict__ cB,
             const float* __restrict__ lg,
             const float* __restrict__ lb,
             unsigned int* __restrict__ hout,
             const int* __restrict__ batch,
             int do_pool, int n) {
    __shared__ float Ws[HID * HID];        // 16 KB
    __shared__ float hs[TR][HID + 2];      // 64x66 fp32 aggregated tile (16.9 KB)
    int t = threadIdx.x;
    for (int i = t; i < HID * HID; i += 256) Ws[i] = W[i];

    int warp = t >> 5, lane = t & 31;
    int node0 = blockIdx.x * TR;

    // ---- Phase 1: aggregation of raw h ----
    for (int i = 0; i < 8; i++) {
        int row = warp * 8 + i;
        int node = node0 + row;
        float ax = 0.f, ay = 0.f;
        if (node < n) {
            int cnt = min(d_cnt[node], CAP);
            const int2* eb = d_bkt + (size_t)node * CAP;
            int e = 0;
            for (; e + 8 <= cnt; e += 8) {
                int4 q0 = ((const int4*)(eb + e))[0];
                int4 q1 = ((const int4*)(eb + e))[1];
                int4 q2 = ((const int4*)(eb + e))[2];
                int4 q3 = ((const int4*)(eb + e))[3];
                unsigned int g0 = __ldg(hin + (size_t)q0.x * 32 + lane);
                unsigned int g1 = __ldg(hin + (size_t)q0.z * 32 + lane);
                unsigned int g2 = __ldg(hin + (size_t)q1.x * 32 + lane);
                unsigned int g3 = __ldg(hin + (size_t)q1.z * 32 + lane);
                unsigned int g4 = __ldg(hin + (size_t)q2.x * 32 + lane);
                unsigned int g5 = __ldg(hin + (size_t)q2.z * 32 + lane);
                unsigned int g6 = __ldg(hin + (size_t)q3.x * 32 + lane);
                unsigned int g7 = __ldg(hin + (size_t)q3.z * 32 + lane);
                float2 v;
                v = h2f(g0); ax += v.x * __int_as_float(q0.y); ay += v.y * __int_as_float(q0.y);
                v = h2f(g1); ax += v.x * __int_as_float(q0.w); ay += v.y * __int_as_float(q0.w);
                v = h2f(g2); ax += v.x * __int_as_float(q1.y); ay += v.y * __int_as_float(q1.y);
                v = h2f(g3); ax += v.x * __int_as_float(q1.w); ay += v.y * __int_as_float(q1.w);
                v = h2f(g4); ax += v.x * __int_as_float(q2.y); ay += v.y * __int_as_float(q2.y);
                v = h2f(g5); ax += v.x * __int_as_float(q2.w); ay += v.y * __int_as_float(q2.w);
                v = h2f(g6); ax += v.x * __int_as_float(q3.y); ay += v.y * __int_as_float(q3.y);
                v = h2f(g7); ax += v.x * __int_as_float(q3.w); ay += v.y * __int_as_float(q3.w);
            }
            for (; e < cnt; e++) {
                int2 p = eb[e];
                unsigned int g = __ldg(hin + (size_t)p.x * 32 + lane);
                float2 v = h2f(g);
                float w = __int_as_float(p.y);
                ax += v.x * w; ay += v.y * w;
            }
        }
        *(float2*)&hs[row][2 * lane] = make_float2(ax, ay);
    }
    __syncthreads();

    // ---- Phase 2: 64x64 GEMM + bias + LN + ReLU ----
    int tx = t & 15;          // col group: cols tx*4 .. tx*4+3
    int ty = t >> 4;          // 0..15 -> rows ty, ty+16, ty+32, ty+48
    float acc[4][4];
#pragma unroll
    for (int r = 0; r < 4; r++)
#pragma unroll
        for (int j = 0; j < 4; j++) acc[r][j] = 0.f;

#pragma unroll 4
    for (int k = 0; k < HID; k++) {
        float4 w4 = *(const float4*)&Ws[k * HID + tx * 4];
        float h0 = hs[ty][k];
        float h1 = hs[ty + 16][k];
        float h2 = hs[ty + 32][k];
        float h3 = hs[ty + 48][k];
        acc[0][0] += h0 * w4.x; acc[0][1] += h0 * w4.y; acc[0][2] += h0 * w4.z; acc[0][3] += h0 * w4.w;
        acc[1][0] += h1 * w4.x; acc[1][1] += h1 * w4.y; acc[1][2] += h1 * w4.z; acc[1][3] += h1 * w4.w;
        acc[2][0] += h2 * w4.x; acc[2][1] += h2 * w4.y; acc[2][2] += h2 * w4.z; acc[2][3] += h2 * w4.w;
        acc[3][0] += h3 * w4.x; acc[3][1] += h3 * w4.y; acc[3][2] += h3 * w4.z; acc[3][3] += h3 * w4.w;
    }

    float4 cb4 = *(const float4*)&cB[tx * 4];
    float4 g4  = *(const float4*)&lg[tx * 4];
    float4 l4  = *(const float4*)&lb[tx * 4];

#pragma unroll
    for (int r = 0; r < 4; r++) {
        int row = ty + 16 * r;
        int node = node0 + row;
        float v0 = acc[r][0] + cb4.x;
        float v1 = acc[r][1] + cb4.y;
        float v2 = acc[r][2] + cb4.z;
        float v3 = acc[r][3] + cb4.w;
        // LN over 64 cols: reduce across the 16-lane tx group (same warp half)
        float s = (v0 + v1) + (v2 + v3);
#pragma unroll
        for (int o = 8; o > 0; o >>= 1) s += __shfl_xor_sync(0xffffffffu, s, o);
        float mu = s * (1.f / 64.f);
        float d0 = v0 - mu, d1 = v1 - mu, d2 = v2 - mu, d3 = v3 - mu;
        float sq = (d0 * d0 + d1 * d1) + (d2 * d2 + d3 * d3);
#pragma unroll
        for (int o = 8; o > 0; o >>= 1) sq += __shfl_xor_sync(0xffffffffu, sq, o);
        float inv = rsqrtf(sq * (1.f / 64.f) + EPSV);
        float r0 = fmaxf(d0 * inv * g4.x + l4.x, 0.f);
        float r1 = fmaxf(d1 * inv * g4.y + l4.y, 0.f);
        float r2 = fmaxf(d2 * inv * g4.z + l4.z, 0.f);
        float r3 = fmaxf(d3 * inv * g4.w + l4.w, 0.f);

        if (node < n) {
            if (do_pool) {
                int b = __ldg(batch + node);
                int c0 = b * HID + tx * 4;
                atomicAdd(&d_psum[c0 + 0], r0);
                atomicAdd(&d_psum[c0 + 1], r1);
                atomicAdd(&d_psum[c0 + 2], r2);
                atomicAdd(&d_psum[c0 + 3], r3);
                atomicMax(&d_pmax[c0 + 0], __float_as_int(r0));
                atomicMax(&d_pmax[c0 + 1], __float_as_int(r1));
                atomicMax(&d_pmax[c0 + 2], __float_as_int(r2));
                atomicMax(&d_pmax[c0 + 3], __float_as_int(r3));
                if (tx == 0) atomicAdd(&d_pcnt[b], 1);
            } else {
                __half2 o0 = __floats2half2_rn(r0, r1);
                __half2 o1 = __floats2half2_rn(r2, r3);
                uint2 ov = make_uint2(*(unsigned int*)&o0, *(unsigned int*)&o1);
                *(uint2*)(hout + (size_t)node * 32 + tx * 2) = ov;
            }
        }
    }
}

// -------- final MLP --------
__global__ void mlp_kernel(const float* __restrict__ W1, const float* __restrict__ b1,
                           const float* __restrict__ W2, const float* __restrict__ b2,
                           float* __restrict__ out) {
    __shared__ float g[2 * HID];
    __shared__ float hr[HID];
    int gi = blockIdx.x, j = threadIdx.x;
    int cnt = d_pcnt[gi];
    float c = fmaxf((float)cnt, 1.f);
    g[j] = d_psum[gi * HID + j] / c;
    g[HID + j] = (cnt > 0) ? __int_as_float(d_pmax[gi * HID + j]) : 0.f;
    __syncthreads();
    float acc = b1[j];
#pragma unroll
    for (int k = 0; k < 2 * HID; k++) acc += g[k] * W1[k * HID + j];
    acc = fmaxf(acc, 0.f);
    hr[j] = acc * W2[j];
    __syncthreads();
    if (j < 32) {
        float s = hr[j] + hr[j + 32];
#pragma unroll
        for (int o = 16; o > 0; o >>= 1) s += __shfl_xor_sync(0xffffffffu, s, o);
        if (j == 0) out[gi] = s + b2[0];
    }
}

extern "C" void kernel_launch(void* const* d_in, const int* in_sizes, int n_in,
                              void* d_out, int out_size) {
    const int*   edge_index = (const int*)d_in[1];
    const float* edge_w     = (const float*)d_in[2];
    const int*   batch      = (const int*)d_in[3];
    const float* emb        = (const float*)d_in[4];
    const float* convW      = (const float*)d_in[5];
    const float* convB      = (const float*)d_in[6];
    const float* lnG        = (const float*)d_in[7];
    const float* lnB        = (const float*)d_in[8];
    const float* W1         = (const float*)d_in[9];
    const float* b1         = (const float*)d_in[10];
    const float* W2         = (const float*)d_in[11];
    const float* b2         = (const float*)d_in[12];
    float* out = (float*)d_out;

    int ne = in_sizes[2];
    int n  = in_sizes[3];
    const int* src = edge_index;
    const int* dst = edge_index + ne;

    unsigned int *hA, *hB;
    cudaGetSymbolAddress((void**)&hA, d_hhA);
    cudaGetSymbolAddress((void**)&hB, d_hhB);

    prep_kernel<<<1184, 256>>>(emb);
    int T = (ne + 3) / 4;
    scatter_kernel<<<(T + 255) / 256, 256>>>(src, dst, edge_w, ne, T);

    const int THREADS = 256;
    int layer_blocks = (n + TR - 1) / TR;   // 782

    // L0: hA -> hB ; L1: hB -> hA ; L2: hA -> pool only
    layer_kernel<<<layer_blocks, THREADS>>>(hA, convW + 0 * HID * HID,
                                            convB + 0 * HID, lnG + 0 * HID,
                                            lnB + 0 * HID, hB, batch, 0, n);
    layer_kernel<<<layer_blocks, THREADS>>>(hB, convW + 1 * HID * HID,
                                            convB + 1 * HID, lnG + 1 * HID,
                                            lnB + 1 * HID, hA, batch, 0, n);
    layer_kernel<<<layer_blocks, THREADS>>>(hA, convW + 2 * HID * HID,
                                            convB + 2 * HID, lnG + 2 * HID,
                                            lnB + 2 * HID, (unsigned int*)nullptr, batch, 1, n);

    mlp_kernel<<<NG, HID>>>(W1, b1, W2, b2, out);
}